// round 13
// baseline (speedup 1.0000x reference)
#include <cuda_runtime.h>
#include <cuda.h>
#include <cuda_fp16.h>
#include <cstdint>
#include <dlfcn.h>
#include <math.h>

// ---------------------------------------------------------------------------
// Problem: B=64, H=W=32, CIN=64, HID=128, K=3, L=3, repeats=3.
// Gates=512, M=65536. Out: [h_last | hs_out(3) | cs_out(3)].
// fp16 operands + fp16 Gx, fp32 accumulate. grid.z = layer (one launch/stage).
// ---------------------------------------------------------------------------
#define BATCH   64
#define HH      32
#define WW      32
#define CIN_X   64
#define HID     128
#define GATES   512
#define MPOS    (BATCH*HH*WW)
#define PLANE   ((size_t)MPOS*HID)
#define GXPLANE ((size_t)MPOS*GATES)
#define KX      (9*CIN_X)              // 576
#define KH      (9*HID)                // 1152

#define BM          256
#define NTH         256
#define STAGES      4
#define A_BYTES     32768
#define B_BYTES     16384
#define STAGE_BYTES (A_BYTES + B_BYTES)
#define SM_A(s)     ((s)*STAGE_BYTES)
#define SM_B(s)     (SM_A(s) + A_BYTES)
#define SM_BAR      (STAGES*STAGE_BYTES)
#define SMEM_TOTAL  (SM_BAR + 128)

// ---------------------------------------------------------------------------
// Device scratch
// ---------------------------------------------------------------------------
__device__ __align__(1024) __half g_WxT[3 * GATES * KX];
__device__ __align__(1024) __half g_WhT[3 * GATES * KH];
__device__ __align__(1024) __half g_xP [(size_t)MPOS * CIN_X];
__device__ __align__(1024) __half g_hsP[3 * PLANE];
__device__ __align__(1024) __half g_Gx [3 * GXPLANE];      // fp16 gate offsets
__device__ __align__(1024) __half g_hbuf[2 * 3 * PLANE];   // [buf][layer]
__device__ __align__(1024) float  g_cbuf[2 * 3 * PLANE];

// ---------------------------------------------------------------------------
// PTX helpers
// ---------------------------------------------------------------------------
__device__ __forceinline__ uint32_t smem_u32(const void* p) {
    uint32_t a;
    asm("{ .reg .u64 t; cvta.to.shared.u64 t, %1; cvt.u32.u64 %0, t; }"
        : "=r"(a) : "l"(p));
    return a;
}
#define MBAR_INIT(addr, cnt) \
    asm volatile("mbarrier.init.shared.b64 [%0], %1;" :: "r"(addr), "r"(cnt) : "memory")
#define MBAR_ARRIVE(addr) \
    asm volatile("mbarrier.arrive.shared.b64 _, [%0];" :: "r"(addr) : "memory")
#define MBAR_EXPECT_TX(addr, bytes) \
    asm volatile("mbarrier.arrive.expect_tx.shared.b64 _, [%0], %1;" \
                 :: "r"(addr), "r"(bytes) : "memory")
#define MBAR_WAIT(addr, ph) do {                                              \
    uint32_t _m = (addr), _p = (ph), _d;                                      \
    asm volatile("{\n\t.reg .pred p;\n\t"                                     \
        "mbarrier.try_wait.parity.acquire.cta.shared::cta.b64 p, [%1], %2;\n\t" \
        "selp.b32 %0, 1, 0, p;\n\t}" : "=r"(_d) : "r"(_m), "r"(_p) : "memory");\
    if (!_d) {                                                                \
        asm volatile("{\n\t.reg .pred P1;\n\tWL_%=:\n\t"                      \
            "mbarrier.try_wait.parity.acquire.cta.shared::cta.b64 P1, [%0], %1, 0x989680;\n\t" \
            "@P1 bra.uni WD_%=;\n\tbra.uni WL_%=;\n\tWD_%=:\n\t}"             \
            :: "r"(_m), "r"(_p) : "memory");                                  \
    } } while (0)

#define TMA_LD_5D(dst, map, c0_, c1_, c2_, c3_, c4_, mbar) \
    asm volatile("cp.async.bulk.tensor.5d.shared::cta.global.tile.mbarrier::complete_tx::bytes " \
        "[%0], [%1, {%2, %3, %4, %5, %6}], [%7];" \
        :: "r"(dst), "l"(map), "r"(c0_), "r"(c1_), "r"(c2_), "r"(c3_), "r"(c4_), "r"(mbar) : "memory")
#define TMA_LD_3D(dst, map, c0_, c1_, c2_, mbar) \
    asm volatile("cp.async.bulk.tensor.3d.shared::cta.global.tile.mbarrier::complete_tx::bytes " \
        "[%0], [%1, {%2, %3, %4}], [%5];" \
        :: "r"(dst), "l"(map), "r"(c0_), "r"(c1_), "r"(c2_), "r"(mbar) : "memory")

__device__ __forceinline__ uint2 lds64(uint32_t addr) {
    uint2 r;
    asm("ld.shared.v2.b32 {%0,%1}, [%2];" : "=r"(r.x), "=r"(r.y) : "r"(addr));
    return r;
}

// m16n8k16 fp16 mma, fp32 accumulate
__device__ __forceinline__ void mma16(float* d, const uint32_t* a, const uint32_t* b) {
    asm volatile("mma.sync.aligned.m16n8k16.row.col.f32.f16.f16.f32 "
        "{%0,%1,%2,%3}, {%4,%5,%6,%7}, {%8,%9}, {%0,%1,%2,%3};"
        : "+f"(d[0]), "+f"(d[1]), "+f"(d[2]), "+f"(d[3])
        : "r"(a[0]), "r"(a[1]), "r"(a[2]), "r"(a[3]), "r"(b[0]), "r"(b[1]));
}

__device__ __forceinline__ int perm16(int k) {
    return 4 * ((k & 7) >> 1) + 2 * (k >> 3) + (k & 1);
}
__device__ __forceinline__ int bankperm64(int c, int row) {
    return ((((c >> 4) & 3) ^ (row & 3)) << 4) | perm16(c & 15);
}
__device__ __forceinline__ float sigm(float v) { return 1.f / (1.f + __expf(-v)); }
// fast accurate tanh: (1-e)/(1+e), e=exp(-2|x|); sign restored. rel err ~1e-6.
__device__ __forceinline__ float tanh_fast(float x) {
    const float e = __expf(-2.f * fabsf(x));
    const float t = (1.f - e) / (1.f + e);
    return copysignf(t, x);
}

// ---------------------------------------------------------------------------
// Fused implicit-GEMM conv via fp16 mma.sync m16n8k16 (fp32 accum).
// grid = (M/BM, 4, 3): blockIdx.z = layer. 8 warps, warp tile 32x128.
// Chunk = 64 fp16 channels. A swizzle key = global x&3 (dx-compensated).
// PERM: h output written fp16 + bank-swizzled (feeds next conv's A).
// add_src: FUSED -> fp16 Gx[M,512] per layer ; else fp32 bias[512] per layer.
// ---------------------------------------------------------------------------
template<int CPT, int NCHUNK, bool FUSED, bool PERM>
__global__ __launch_bounds__(NTH, 1)
void conv_tc(const __grid_constant__ CUtensorMap a_map,
             const __grid_constant__ CUtensorMap b_map,
             int a_z0, int a_zstep,
             const char* __restrict__ add_src, size_t add_stride,
             const char* __restrict__ c_in,    size_t cin_stride,
             char* __restrict__ out0,          size_t out0_stride,
             char* __restrict__ c_out,         size_t cout_stride,
             float* __restrict__ h_dup)        // only used when layer==2
{
    extern __shared__ __align__(1024) char smem[];
    const uint32_t sb = smem_u32(smem);
    const int tid  = threadIdx.x;
    const int lane = tid & 31;
    const int wm   = tid >> 5;
    const int l    = blockIdx.z;
    const int a_z  = a_z0 + l * a_zstep;
    const int b_z  = l;

    const uint32_t FULL  = sb + SM_BAR;
    const uint32_t EMPTY = sb + SM_BAR + 32;

    if (tid == 0) {
#pragma unroll
        for (int s = 0; s < STAGES; s++) {
            MBAR_INIT(FULL + 8*s, 1);
            MBAR_INIT(EMPTY + 8*s, 8);
        }
    }
    __syncthreads();

    const int c0   = blockIdx.y * 32;
    const int m0   = blockIdx.x * BM;
    const int bimg = m0 >> 10;
    const int y0   = (m0 >> 5) & 31;

    if (tid == 0) {
#pragma unroll
        for (int kc = 0; kc < STAGES; kc++) {
            const int s = kc;
            MBAR_EXPECT_TX(FULL + 8*s, (uint32_t)STAGE_BYTES);
            const int tap = kc / CPT, cc = (kc % CPT) * 64;
            const int dy = tap / 3 - 1, dx = tap % 3 - 1;
            TMA_LD_5D(sb + SM_A(s), &a_map, cc, dx, y0 + dy, bimg, a_z, FULL + 8*s);
            const int k0 = kc * 64;
#pragma unroll
            for (int g = 0; g < 4; g++)
                TMA_LD_3D(sb + SM_B(s) + g * 4096, &b_map, k0, g * 128 + c0, b_z,
                          FULL + 8*s);
        }
    }

    float acc[2][16][4];
#pragma unroll
    for (int mi = 0; mi < 2; mi++)
#pragma unroll
        for (int ni = 0; ni < 16; ni++)
#pragma unroll
            for (int j = 0; j < 4; j++) acc[mi][ni][j] = 0.f;

    const int q4 = lane >> 2;
    const int t4 = lane & 3;
    const uint32_t xorB = (uint32_t)(q4 & 3) << 5;

    for (int kc = 0; kc < NCHUNK; kc++) {
        const int s = kc & 3;
        const uint32_t u = (kc >> 2) & 1;
        MBAR_WAIT(FULL + 8*s, u);

        const int tap = kc / CPT;
        const int dxA = tap % 3 - 1;
        const uint32_t xorA = (uint32_t)((q4 + dxA) & 3) << 5;

        const uint32_t aW = sb + SM_A(s) + (uint32_t)wm * 4096 + ((uint32_t)q4 << 7);
        const uint32_t bW = sb + SM_B(s) + ((uint32_t)q4 << 7);

#pragma unroll
        for (int ks = 0; ks < 4; ks++) {
            const uint32_t koffA = (((uint32_t)(ks * 32)) ^ xorA) + (uint32_t)(t4 * 8);
            const uint32_t koffB = (((uint32_t)(ks * 32)) ^ xorB) + (uint32_t)(t4 * 8);

            uint2 aLo[2], aHi[2];
#pragma unroll
            for (int mi = 0; mi < 2; mi++) {
                aLo[mi] = lds64(aW + (uint32_t)mi * 2048 + koffA);
                aHi[mi] = lds64(aW + (uint32_t)mi * 2048 + 1024 + koffA);
            }
            uint2 bfr[16];
#pragma unroll
            for (int ni = 0; ni < 16; ni++)
                bfr[ni] = lds64(bW + (uint32_t)(ni >> 2) * 4096
                                   + (uint32_t)(ni & 3) * 1024 + koffB);
#pragma unroll
            for (int mi = 0; mi < 2; mi++) {
                const uint32_t af[4] = {aLo[mi].x, aHi[mi].x, aLo[mi].y, aHi[mi].y};
#pragma unroll
                for (int ni = 0; ni < 16; ni++)
                    mma16(acc[mi][ni], af, &bfr[ni].x);
            }
        }

        if (lane == 0) MBAR_ARRIVE(EMPTY + 8*s);

        if (tid == 0 && kc + STAGES < NCHUNK) {
            MBAR_WAIT(EMPTY + 8*s, u);
            MBAR_EXPECT_TX(FULL + 8*s, (uint32_t)STAGE_BYTES);
            const int kn = kc + STAGES;
            const int tapn = kn / CPT, cc = (kn % CPT) * 64;
            const int dy = tapn / 3 - 1, dx = tapn % 3 - 1;
            TMA_LD_5D(sb + SM_A(s), &a_map, cc, dx, y0 + dy, bimg, a_z, FULL + 8*s);
            const int k0 = kn * 64;
#pragma unroll
            for (int g = 0; g < 4; g++)
                TMA_LD_3D(sb + SM_B(s) + g * 4096, &b_map, k0, g * 128 + c0, b_z,
                          FULL + 8*s);
        }
    }

    // ------------------------- epilogue -------------------------
    if (FUSED) {
        const __half* gxl = (const __half*)(add_src + (size_t)l * add_stride);
        const float*  cil = (const float*)(c_in + (size_t)l * cin_stride);
        float*  coutl = (float*)(c_out + (size_t)l * cout_stride);
        __half* o16   = (__half*)(out0 + (size_t)l * out0_stride);
        float*  o32   = (float*)(out0 + (size_t)l * out0_stride);
        float*  hd    = (h_dup && l == 2) ? h_dup : nullptr;
#pragma unroll
        for (int mi = 0; mi < 2; mi++)
#pragma unroll
            for (int h = 0; h < 2; h++) {
                const int m = m0 + wm * 32 + mi * 16 + q4 + 8 * h;
                const int j = 2 * h;
#pragma unroll
                for (int nq = 0; nq < 4; nq++) {
                    const int ch = c0 + nq * 8 + t4 * 2;
                    const __half* gxp = gxl + (size_t)m * GATES + ch;
                    const float2 gi = __half22float2(*(const half2*)(gxp));
                    const float2 gf = __half22float2(*(const half2*)(gxp + 128));
                    const float2 gg = __half22float2(*(const half2*)(gxp + 256));
                    const float2 go = __half22float2(*(const half2*)(gxp + 384));
                    const float2 cv = *(const float2*)(cil + (size_t)m * HID + ch);

                    const float i0 = acc[mi][nq][j]      + gi.x;
                    const float i1 = acc[mi][nq][j+1]    + gi.y;
                    const float f0 = acc[mi][4+nq][j]    + gf.x;
                    const float f1 = acc[mi][4+nq][j+1]  + gf.y;
                    const float g0 = acc[mi][8+nq][j]    + gg.x;
                    const float g1 = acc[mi][8+nq][j+1]  + gg.y;
                    const float o0 = acc[mi][12+nq][j]   + go.x;
                    const float o1 = acc[mi][12+nq][j+1] + go.y;

                    float2 cn, hn;
                    cn.x = sigm(f0) * cv.x + sigm(i0) * tanh_fast(g0);
                    cn.y = sigm(f1) * cv.y + sigm(i1) * tanh_fast(g1);
                    hn.x = sigm(o0) * tanh_fast(cn.x);
                    hn.y = sigm(o1) * tanh_fast(cn.y);

                    const size_t ob = (size_t)m * HID + ch;
                    *(float2*)(coutl + ob) = cn;
                    if (PERM) {
                        const int c64 = ch & 63;
                        const int G   = (c64 >> 4) ^ (m & 3);
                        const int a2  = (c64 & 15) >> 1;
                        const int p   = 4 * (a2 & 3) + 2 * (a2 >> 2);
                        const int pos = (ch & ~63) + (G << 4) + p;
                        *(half2*)(o16 + (size_t)m * HID + pos) =
                            __floats2half2_rn(hn.x, hn.y);
                    } else {
                        *(float2*)(o32 + ob) = hn;
                        if (hd) *(float2*)(hd + ob) = hn;
                    }
                }
            }
    } else {
        // x-conv epilogue: Gx = acc + bias, stored fp16
        const float* bl = (const float*)(add_src + (size_t)l * add_stride);
        __half* gxo = (__half*)(out0 + (size_t)l * out0_stride);
#pragma unroll
        for (int mi = 0; mi < 2; mi++)
#pragma unroll
            for (int h = 0; h < 2; h++) {
                const int m = m0 + wm * 32 + mi * 16 + q4 + 8 * h;
                const int j = 2 * h;
#pragma unroll
                for (int ni = 0; ni < 16; ni++) {
                    const int gcol = (ni >> 2) * 128 + c0 + (ni & 3) * 8 + t4 * 2;
                    const float2 bv = *(const float2*)(bl + gcol);
                    *(half2*)(gxo + (size_t)m * GATES + gcol) =
                        __floats2half2_rn(acc[mi][ni][j] + bv.x,
                                          acc[mi][ni][j+1] + bv.y);
                }
            }
    }
}

// ---------------------------------------------------------------------------
// Pre-passes: fp32 -> fp16 with bank-swizzled 64-channel K layout.
// ---------------------------------------------------------------------------
__global__ void prep_w(const float* __restrict__ src, __half* __restrict__ dst,
                       int K, int total)
{
    int i = blockIdx.x * blockDim.x + threadIdx.x;
    if (i >= total) return;
    int n = i % GATES;
    int k = (i / GATES) % K;
    int l = i / (GATES * K);
    int kp = (k & ~63) | bankperm64(k & 63, n);
    dst[((size_t)l * GATES + n) * K + kp] = __float2half_rn(src[i]);
}

__global__ void prep_a2(const float* __restrict__ src, __half* __restrict__ dst,
                        int Cpairs, size_t totalPairs)
{
    size_t i = (size_t)blockIdx.x * blockDim.x + threadIdx.x;
    if (i >= totalPairs) return;
    const int cp2 = (int)(i % (size_t)Cpairs);
    const size_t row = i / (size_t)Cpairs;
    const int c = cp2 * 2;
    const int key = (int)(row & 3);
    const int pos = (c & ~63) | bankperm64(c & 63, key);
    const float2 v = *(const float2*)(src + row * (size_t)(Cpairs * 2) + c);
    *(half2*)(dst + row * (size_t)(Cpairs * 2) + pos) = __floats2half2_rn(v.x, v.y);
}

// ---------------------------------------------------------------------------
// Host: tensormap encoding via dlopen
// ---------------------------------------------------------------------------
typedef CUresult (*EncFn)(CUtensorMap*, CUtensorMapDataType, cuuint32_t, void*,
                          const cuuint64_t*, const cuuint64_t*, const cuuint32_t*,
                          const cuuint32_t*, CUtensorMapInterleave, CUtensorMapSwizzle,
                          CUtensorMapL2promotion, CUtensorMapFloatOOBfill);
static EncFn get_enc() {
    static EncFn f = nullptr;
    if (!f) {
        void* h = dlopen("libcuda.so.1", RTLD_NOW | RTLD_GLOBAL);
        if (!h) h = dlopen("libcuda.so", RTLD_NOW | RTLD_GLOBAL);
        if (h) f = (EncFn)dlsym(h, "cuTensorMapEncodeTiled");
    }
    return f;
}

static void enc_act5(CUtensorMap* tm, void* base, int C, int Z) {
    cuuint64_t dims[5]    = {(cuuint64_t)C, WW, HH, BATCH, (cuuint64_t)Z};
    cuuint64_t strides[4] = {(cuuint64_t)C * 2, (cuuint64_t)WW * C * 2,
                             (cuuint64_t)HH * WW * C * 2,
                             (cuuint64_t)BATCH * HH * WW * C * 2};
    cuuint32_t box[5] = {64, WW, 8, 1, 1};
    cuuint32_t es[5]  = {1, 1, 1, 1, 1};
    get_enc()(tm, CU_TENSOR_MAP_DATA_TYPE_FLOAT16, 5, base, dims, strides, box, es,
              CU_TENSOR_MAP_INTERLEAVE_NONE, CU_TENSOR_MAP_SWIZZLE_NONE,
              CU_TENSOR_MAP_L2_PROMOTION_L2_128B, CU_TENSOR_MAP_FLOAT_OOB_FILL_NONE);
}
static void enc_w3(CUtensorMap* tm, void* base, int K) {
    cuuint64_t dims[3]    = {(cuuint64_t)K, GATES, 3};
    cuuint64_t strides[2] = {(cuuint64_t)K * 2, (cuuint64_t)GATES * K * 2};
    cuuint32_t box[3] = {64, 32, 1};
    cuuint32_t es[3]  = {1, 1, 1};
    get_enc()(tm, CU_TENSOR_MAP_DATA_TYPE_FLOAT16, 3, base, dims, strides, box, es,
              CU_TENSOR_MAP_INTERLEAVE_NONE, CU_TENSOR_MAP_SWIZZLE_NONE,
              CU_TENSOR_MAP_L2_PROMOTION_L2_128B, CU_TENSOR_MAP_FLOAT_OOB_FILL_NONE);
}

extern "C" void kernel_launch(void* const* d_in, const int* in_sizes, int n_in,
                              void* d_out, int out_size)
{
    const float* x  = (const float*)d_in[0];
    const float* hs = (const float*)d_in[1];
    const float* cs = (const float*)d_in[2];
    const float* Wx = (const float*)d_in[3];
    const float* Wh = (const float*)d_in[4];
    const float* bb = (const float*)d_in[5];

    float* out    = (float*)d_out;
    float* h_last = out;
    float* hs_out = out + PLANE;
    float* cs_out = out + 4 * PLANE;

    __half *WxT, *WhT, *xP, *hsP, *hbuf, *Gx;
    float  *cbuf;
    cudaGetSymbolAddress((void**)&WxT,  g_WxT);
    cudaGetSymbolAddress((void**)&WhT,  g_WhT);
    cudaGetSymbolAddress((void**)&xP,   g_xP);
    cudaGetSymbolAddress((void**)&hsP,  g_hsP);
    cudaGetSymbolAddress((void**)&Gx,   g_Gx);
    cudaGetSymbolAddress((void**)&hbuf, g_hbuf);
    cudaGetSymbolAddress((void**)&cbuf, g_cbuf);

    cudaFuncSetAttribute(conv_tc<1, 9, false, false>,
                         cudaFuncAttributeMaxDynamicSharedMemorySize, SMEM_TOTAL);
    cudaFuncSetAttribute(conv_tc<2, 18, true, true>,
                         cudaFuncAttributeMaxDynamicSharedMemorySize, SMEM_TOTAL);
    cudaFuncSetAttribute(conv_tc<2, 18, true, false>,
                         cudaFuncAttributeMaxDynamicSharedMemorySize, SMEM_TOTAL);

    CUtensorMap tm_x, tm_hs, tm_hb, tm_wx, tm_wh;
    enc_act5(&tm_x,  xP,   CIN_X, 1);
    enc_act5(&tm_hs, hsP,  HID,   3);
    enc_act5(&tm_hb, hbuf, HID,   6);   // [buf0 l0..l2 | buf1 l0..l2]
    enc_w3(&tm_wx, WxT, KX);
    enc_w3(&tm_wh, WhT, KH);

    // pre-passes
    {
        int tw = 3 * KX * GATES, th = 3 * KH * GATES;
        prep_w<<<(tw + 255) / 256, 256>>>(Wx, WxT, KX, tw);
        prep_w<<<(th + 255) / 256, 256>>>(Wh, WhT, KH, th);
        size_t px = (size_t)MPOS * (CIN_X / 2), ph = 3 * PLANE / 2;
        prep_a2<<<(unsigned)((px + 255) / 256), 256>>>(x,  xP,  CIN_X / 2, px);
        prep_a2<<<(unsigned)((ph + 255) / 256), 256>>>(hs, hsP, HID / 2,  ph);
    }

    const dim3 grid(MPOS / BM, 4, 3);        // all 3 layers per launch
    const size_t gxS = GXPLANE * 2;          // Gx per-layer bytes (fp16)
    const size_t pF  = PLANE * 4;            // fp32 plane bytes
    const size_t pH  = PLANE * 2;            // fp16 plane bytes

    // Gx[l] = conv(x, Wx[l]) + b[l]   (repeat-invariant; fp16 store)
    conv_tc<1, 9, false, false><<<grid, NTH, SMEM_TOTAL>>>(
        tm_x, tm_wx, 0, 0,
        (const char*)bb, GATES * 4,
        nullptr, 0,
        (char*)Gx, gxS,
        nullptr, 0, nullptr);

    // r0: hsP[l]/cs[l] -> hbuf[0][l] (fp16 perm) / cbuf[0][l]
    conv_tc<2, 18, true, true><<<grid, NTH, SMEM_TOTAL>>>(
        tm_hs, tm_wh, 0, 1,
        (const char*)Gx, gxS,
        (const char*)cs, pF,
        (char*)hbuf, pH,
        (char*)cbuf, pF, nullptr);

    // r1: hbuf[0][l]/cbuf[0][l] -> hbuf[1][l] / cbuf[1][l]
    conv_tc<2, 18, true, true><<<grid, NTH, SMEM_TOTAL>>>(
        tm_hb, tm_wh, 0, 1,
        (const char*)Gx, gxS,
        (const char*)cbuf, pF,
        (char*)(hbuf + 3 * PLANE), pH,
        (char*)(cbuf + 3 * PLANE), pF, nullptr);

    // r2: hbuf[1][l]/cbuf[1][l] -> output slices (fp32, natural order)
    conv_tc<2, 18, true, false><<<grid, NTH, SMEM_TOTAL>>>(
        tm_hb, tm_wh, 3, 1,
        (const char*)Gx, gxS,
        (const char*)(cbuf + 3 * PLANE), pF,
        (char*)hs_out, pF,
        (char*)cs_out, pF, h_last);
}

// round 14
// speedup vs baseline: 1.1031x; 1.1031x over previous
#include <cuda_runtime.h>
#include <cuda.h>
#include <cuda_fp16.h>
#include <cstdint>
#include <dlfcn.h>
#include <math.h>

// ---------------------------------------------------------------------------
// Problem: B=64, H=W=32, CIN=64, HID=128, K=3, L=3, repeats=3.
// Gates=512, M=65536. Out: [h_last | hs_out(3) | cs_out(3)].
// fp16 operands, fp32 accumulate/Gx. grid.z = layer (one launch per stage).
// Warp tile 64x64: 8 warps = 4(M) x 2(N) -- minimizes smem bytes per chunk.
// ---------------------------------------------------------------------------
#define BATCH   64
#define HH      32
#define WW      32
#define CIN_X   64
#define HID     128
#define GATES   512
#define MPOS    (BATCH*HH*WW)
#define PLANE   ((size_t)MPOS*HID)
#define GXPLANE ((size_t)MPOS*GATES)
#define KX      (9*CIN_X)              // 576
#define KH      (9*HID)                // 1152

#define BM          256
#define NTH         256
#define STAGES      4
#define A_BYTES     32768
#define B_BYTES     16384
#define STAGE_BYTES (A_BYTES + B_BYTES)
#define SM_A(s)     ((s)*STAGE_BYTES)
#define SM_B(s)     (SM_A(s) + A_BYTES)
#define SM_BAR      (STAGES*STAGE_BYTES)
#define SMEM_TOTAL  (SM_BAR + 128)

// ---------------------------------------------------------------------------
// Device scratch
// ---------------------------------------------------------------------------
__device__ __align__(1024) __half g_WxT[3 * GATES * KX];
__device__ __align__(1024) __half g_WhT[3 * GATES * KH];
__device__ __align__(1024) __half g_xP [(size_t)MPOS * CIN_X];
__device__ __align__(1024) __half g_hsP[3 * PLANE];
__device__ __align__(1024) float  g_Gx [3 * GXPLANE];
__device__ __align__(1024) __half g_hbuf[2 * 3 * PLANE];   // [buf][layer]
__device__ __align__(1024) float  g_cbuf[2 * 3 * PLANE];

// ---------------------------------------------------------------------------
// PTX helpers
// ---------------------------------------------------------------------------
__device__ __forceinline__ uint32_t smem_u32(const void* p) {
    uint32_t a;
    asm("{ .reg .u64 t; cvta.to.shared.u64 t, %1; cvt.u32.u64 %0, t; }"
        : "=r"(a) : "l"(p));
    return a;
}
#define MBAR_INIT(addr, cnt) \
    asm volatile("mbarrier.init.shared.b64 [%0], %1;" :: "r"(addr), "r"(cnt) : "memory")
#define MBAR_ARRIVE(addr) \
    asm volatile("mbarrier.arrive.shared.b64 _, [%0];" :: "r"(addr) : "memory")
#define MBAR_EXPECT_TX(addr, bytes) \
    asm volatile("mbarrier.arrive.expect_tx.shared.b64 _, [%0], %1;" \
                 :: "r"(addr), "r"(bytes) : "memory")
#define MBAR_WAIT(addr, ph) do {                                              \
    uint32_t _m = (addr), _p = (ph), _d;                                      \
    asm volatile("{\n\t.reg .pred p;\n\t"                                     \
        "mbarrier.try_wait.parity.acquire.cta.shared::cta.b64 p, [%1], %2;\n\t" \
        "selp.b32 %0, 1, 0, p;\n\t}" : "=r"(_d) : "r"(_m), "r"(_p) : "memory");\
    if (!_d) {                                                                \
        asm volatile("{\n\t.reg .pred P1;\n\tWL_%=:\n\t"                      \
            "mbarrier.try_wait.parity.acquire.cta.shared::cta.b64 P1, [%0], %1, 0x989680;\n\t" \
            "@P1 bra.uni WD_%=;\n\tbra.uni WL_%=;\n\tWD_%=:\n\t}"             \
            :: "r"(_m), "r"(_p) : "memory");                                  \
    } } while (0)

#define TMA_LD_5D(dst, map, c0_, c1_, c2_, c3_, c4_, mbar) \
    asm volatile("cp.async.bulk.tensor.5d.shared::cta.global.tile.mbarrier::complete_tx::bytes " \
        "[%0], [%1, {%2, %3, %4, %5, %6}], [%7];" \
        :: "r"(dst), "l"(map), "r"(c0_), "r"(c1_), "r"(c2_), "r"(c3_), "r"(c4_), "r"(mbar) : "memory")
#define TMA_LD_3D(dst, map, c0_, c1_, c2_, mbar) \
    asm volatile("cp.async.bulk.tensor.3d.shared::cta.global.tile.mbarrier::complete_tx::bytes " \
        "[%0], [%1, {%2, %3, %4}], [%5];" \
        :: "r"(dst), "l"(map), "r"(c0_), "r"(c1_), "r"(c2_), "r"(mbar) : "memory")

__device__ __forceinline__ uint2 lds64(uint32_t addr) {
    uint2 r;
    asm("ld.shared.v2.b32 {%0,%1}, [%2];" : "=r"(r.x), "=r"(r.y) : "r"(addr));
    return r;
}

// m16n8k16 fp16 mma, fp32 accumulate
__device__ __forceinline__ void mma16(float* d, const uint32_t* a, const uint32_t* b) {
    asm volatile("mma.sync.aligned.m16n8k16.row.col.f32.f16.f16.f32 "
        "{%0,%1,%2,%3}, {%4,%5,%6,%7}, {%8,%9}, {%0,%1,%2,%3};"
        : "+f"(d[0]), "+f"(d[1]), "+f"(d[2]), "+f"(d[3])
        : "r"(a[0]), "r"(a[1]), "r"(a[2]), "r"(a[3]), "r"(b[0]), "r"(b[1]));
}

__device__ __forceinline__ int perm16(int k) {
    return 4 * ((k & 7) >> 1) + 2 * (k >> 3) + (k & 1);
}
__device__ __forceinline__ int bankperm64(int c, int row) {
    return ((((c >> 4) & 3) ^ (row & 3)) << 4) | perm16(c & 15);
}
__device__ __forceinline__ float sigm(float v) { return 1.f / (1.f + __expf(-v)); }

// ---------------------------------------------------------------------------
// Fused implicit-GEMM conv via fp16 mma.sync m16n8k16 (fp32 accum).
// grid = (M/BM, 4, 3): blockIdx.z = layer. 8 warps = 4(M) x 2(N), tile 64x64.
// Chunk = 64 fp16 channels. A swizzle key = global x&3 (dx-compensated).
// Each warp owns 2 sub-columns of EVERY gate -> fused epilogue thread-local.
// ---------------------------------------------------------------------------
template<int CPT, int NCHUNK, bool FUSED, bool PERM>
__global__ __launch_bounds__(NTH, 1)
void conv_tc(const __grid_constant__ CUtensorMap a_map,
             const __grid_constant__ CUtensorMap b_map,
             int a_z0, int a_zstep,
             const char* __restrict__ add_src, size_t add_stride,
             const char* __restrict__ c_in,    size_t cin_stride,
             char* __restrict__ out0,          size_t out0_stride,
             char* __restrict__ c_out,         size_t cout_stride,
             float* __restrict__ h_dup)        // only used when layer==2
{
    extern __shared__ __align__(1024) char smem[];
    const uint32_t sb = smem_u32(smem);
    const int tid  = threadIdx.x;
    const int lane = tid & 31;
    const int wid  = tid >> 5;
    const int wm4  = wid & 3;            // M slice (64 rows)
    const int wn   = wid >> 2;           // N half (0/1): 16 channels per gate
    const int l    = blockIdx.z;
    const int a_z  = a_z0 + l * a_zstep;
    const int b_z  = l;

    const uint32_t FULL  = sb + SM_BAR;
    const uint32_t EMPTY = sb + SM_BAR + 32;

    if (tid == 0) {
#pragma unroll
        for (int s = 0; s < STAGES; s++) {
            MBAR_INIT(FULL + 8*s, 1);
            MBAR_INIT(EMPTY + 8*s, 8);
        }
    }
    __syncthreads();

    const int c0   = blockIdx.y * 32;
    const int m0   = blockIdx.x * BM;
    const int bimg = m0 >> 10;
    const int y0   = (m0 >> 5) & 31;

    if (tid == 0) {
#pragma unroll
        for (int kc = 0; kc < STAGES; kc++) {
            const int s = kc;
            MBAR_EXPECT_TX(FULL + 8*s, (uint32_t)STAGE_BYTES);
            const int tap = kc / CPT, cc = (kc % CPT) * 64;
            const int dy = tap / 3 - 1, dx = tap % 3 - 1;
            TMA_LD_5D(sb + SM_A(s), &a_map, cc, dx, y0 + dy, bimg, a_z, FULL + 8*s);
            const int k0 = kc * 64;
#pragma unroll
            for (int g = 0; g < 4; g++)
                TMA_LD_3D(sb + SM_B(s) + g * 4096, &b_map, k0, g * 128 + c0, b_z,
                          FULL + 8*s);
        }
    }

    float acc[4][8][4];   // [mi][g*2+s2][frag]
#pragma unroll
    for (int mi = 0; mi < 4; mi++)
#pragma unroll
        for (int ni = 0; ni < 8; ni++)
#pragma unroll
            for (int j = 0; j < 4; j++) acc[mi][ni][j] = 0.f;

    const int q4 = lane >> 2;
    const int t4 = lane & 3;
    const uint32_t xorB = (uint32_t)(q4 & 3) << 5;

    for (int kc = 0; kc < NCHUNK; kc++) {
        const int s = kc & 3;
        const uint32_t u = (kc >> 2) & 1;
        MBAR_WAIT(FULL + 8*s, u);

        const int tap = kc / CPT;
        const int dxA = tap % 3 - 1;
        const uint32_t xorA = (uint32_t)((q4 + dxA) & 3) << 5;

        const uint32_t aW = sb + SM_A(s) + (uint32_t)wm4 * 8192 + ((uint32_t)q4 << 7);
        const uint32_t bW = sb + SM_B(s) + (uint32_t)wn * 2048 + ((uint32_t)q4 << 7);

#pragma unroll
        for (int ks = 0; ks < 4; ks++) {
            const uint32_t koffA = (((uint32_t)(ks * 32)) ^ xorA) + (uint32_t)(t4 * 8);
            const uint32_t koffB = (((uint32_t)(ks * 32)) ^ xorB) + (uint32_t)(t4 * 8);

            uint2 aLo[4], aHi[4];
#pragma unroll
            for (int mi = 0; mi < 4; mi++) {
                aLo[mi] = lds64(aW + (uint32_t)mi * 2048 + koffA);
                aHi[mi] = lds64(aW + (uint32_t)mi * 2048 + 1024 + koffA);
            }
            uint2 bfr[8];
#pragma unroll
            for (int g = 0; g < 4; g++)
#pragma unroll
                for (int s2 = 0; s2 < 2; s2++)
                    bfr[g*2+s2] = lds64(bW + (uint32_t)g * 4096
                                           + (uint32_t)s2 * 1024 + koffB);
#pragma unroll
            for (int mi = 0; mi < 4; mi++) {
                const uint32_t af[4] = {aLo[mi].x, aHi[mi].x, aLo[mi].y, aHi[mi].y};
#pragma unroll
                for (int ni = 0; ni < 8; ni++)
                    mma16(acc[mi][ni], af, &bfr[ni].x);
            }
        }

        if (lane == 0) MBAR_ARRIVE(EMPTY + 8*s);

        if (tid == 0 && kc + STAGES < NCHUNK) {
            MBAR_WAIT(EMPTY + 8*s, u);
            MBAR_EXPECT_TX(FULL + 8*s, (uint32_t)STAGE_BYTES);
            const int kn = kc + STAGES;
            const int tapn = kn / CPT, cc = (kn % CPT) * 64;
            const int dy = tapn / 3 - 1, dx = tapn % 3 - 1;
            TMA_LD_5D(sb + SM_A(s), &a_map, cc, dx, y0 + dy, bimg, a_z, FULL + 8*s);
            const int k0 = kn * 64;
#pragma unroll
            for (int g = 0; g < 4; g++)
                TMA_LD_3D(sb + SM_B(s) + g * 4096, &b_map, k0, g * 128 + c0, b_z,
                          FULL + 8*s);
        }
    }

    // ------------------------- epilogue -------------------------
    if (FUSED) {
        const float* gxl = (const float*)(add_src + (size_t)l * add_stride);
        const float* cil = (const float*)(c_in + (size_t)l * cin_stride);
        float*  coutl = (float*)(c_out + (size_t)l * cout_stride);
        __half* o16   = (__half*)(out0 + (size_t)l * out0_stride);
        float*  o32   = (float*)(out0 + (size_t)l * out0_stride);
        float*  hd    = (h_dup && l == 2) ? h_dup : nullptr;
#pragma unroll
        for (int mi = 0; mi < 4; mi++)
#pragma unroll
            for (int h = 0; h < 2; h++) {
                const int m = m0 + wm4 * 64 + mi * 16 + q4 + 8 * h;
                const int j = 2 * h;
#pragma unroll
                for (int s2 = 0; s2 < 2; s2++) {
                    const int nqe = wn * 2 + s2;
                    const int ch = c0 + nqe * 8 + t4 * 2;
                    const float* gxp = gxl + (size_t)m * GATES + ch;
                    const float2 gi = *(const float2*)(gxp);
                    const float2 gf = *(const float2*)(gxp + 128);
                    const float2 gg = *(const float2*)(gxp + 256);
                    const float2 go = *(const float2*)(gxp + 384);
                    const float2 cv = *(const float2*)(cil + (size_t)m * HID + ch);

                    const float i0 = acc[mi][s2][j]      + gi.x;
                    const float i1 = acc[mi][s2][j+1]    + gi.y;
                    const float f0 = acc[mi][2+s2][j]    + gf.x;
                    const float f1 = acc[mi][2+s2][j+1]  + gf.y;
                    const float g0 = acc[mi][4+s2][j]    + gg.x;
                    const float g1 = acc[mi][4+s2][j+1]  + gg.y;
                    const float o0 = acc[mi][6+s2][j]    + go.x;
                    const float o1 = acc[mi][6+s2][j+1]  + go.y;

                    float2 cn, hn;
                    cn.x = sigm(f0) * cv.x + sigm(i0) * tanhf(g0);
                    cn.y = sigm(f1) * cv.y + sigm(i1) * tanhf(g1);
                    hn.x = sigm(o0) * tanhf(cn.x);
                    hn.y = sigm(o1) * tanhf(cn.y);

                    const size_t ob = (size_t)m * HID + ch;
                    *(float2*)(coutl + ob) = cn;
                    if (PERM) {
                        const int c64 = ch & 63;
                        const int G   = (c64 >> 4) ^ (m & 3);
                        const int a2  = (c64 & 15) >> 1;
                        const int p   = 4 * (a2 & 3) + 2 * (a2 >> 2);
                        const int pos = (ch & ~63) + (G << 4) + p;
                        *(half2*)(o16 + (size_t)m * HID + pos) =
                            __floats2half2_rn(hn.x, hn.y);
                    } else {
                        *(float2*)(o32 + ob) = hn;
                        if (hd) *(float2*)(hd + ob) = hn;
                    }
                }
            }
    } else {
        const float* bl = (const float*)(add_src + (size_t)l * add_stride);
        float* gxo = (float*)(out0 + (size_t)l * out0_stride);
#pragma unroll
        for (int mi = 0; mi < 4; mi++)
#pragma unroll
            for (int h = 0; h < 2; h++) {
                const int m = m0 + wm4 * 64 + mi * 16 + q4 + 8 * h;
                const int j = 2 * h;
#pragma unroll
                for (int g = 0; g < 4; g++)
#pragma unroll
                    for (int s2 = 0; s2 < 2; s2++) {
                        const int gcol = g * 128 + c0 + (wn * 2 + s2) * 8 + t4 * 2;
                        const float2 bv = *(const float2*)(bl + gcol);
                        float2 v;
                        v.x = acc[mi][g*2+s2][j]   + bv.x;
                        v.y = acc[mi][g*2+s2][j+1] + bv.y;
                        *(float2*)(gxo + (size_t)m * GATES + gcol) = v;
                    }
            }
    }
}

// ---------------------------------------------------------------------------
// Pre-passes: fp32 -> fp16 with bank-swizzled 64-channel K layout.
// ---------------------------------------------------------------------------
__global__ void prep_w(const float* __restrict__ src, __half* __restrict__ dst,
                       int K, int total)
{
    int i = blockIdx.x * blockDim.x + threadIdx.x;
    if (i >= total) return;
    int n = i % GATES;
    int k = (i / GATES) % K;
    int l = i / (GATES * K);
    int kp = (k & ~63) | bankperm64(k & 63, n);
    dst[((size_t)l * GATES + n) * K + kp] = __float2half_rn(src[i]);
}

__global__ void prep_a2(const float* __restrict__ src, __half* __restrict__ dst,
                        int Cpairs, size_t totalPairs)
{
    size_t i = (size_t)blockIdx.x * blockDim.x + threadIdx.x;
    if (i >= totalPairs) return;
    const int cp2 = (int)(i % (size_t)Cpairs);
    const size_t row = i / (size_t)Cpairs;
    const int c = cp2 * 2;
    const int key = (int)(row & 3);
    const int pos = (c & ~63) | bankperm64(c & 63, key);
    const float2 v = *(const float2*)(src + row * (size_t)(Cpairs * 2) + c);
    *(half2*)(dst + row * (size_t)(Cpairs * 2) + pos) = __floats2half2_rn(v.x, v.y);
}

// ---------------------------------------------------------------------------
// Host: tensormap encoding via dlopen
// ---------------------------------------------------------------------------
typedef CUresult (*EncFn)(CUtensorMap*, CUtensorMapDataType, cuuint32_t, void*,
                          const cuuint64_t*, const cuuint64_t*, const cuuint32_t*,
                          const cuuint32_t*, CUtensorMapInterleave, CUtensorMapSwizzle,
                          CUtensorMapL2promotion, CUtensorMapFloatOOBfill);
static EncFn get_enc() {
    static EncFn f = nullptr;
    if (!f) {
        void* h = dlopen("libcuda.so.1", RTLD_NOW | RTLD_GLOBAL);
        if (!h) h = dlopen("libcuda.so", RTLD_NOW | RTLD_GLOBAL);
        if (h) f = (EncFn)dlsym(h, "cuTensorMapEncodeTiled");
    }
    return f;
}

static void enc_act5(CUtensorMap* tm, void* base, int C, int Z) {
    cuuint64_t dims[5]    = {(cuuint64_t)C, WW, HH, BATCH, (cuuint64_t)Z};
    cuuint64_t strides[4] = {(cuuint64_t)C * 2, (cuuint64_t)WW * C * 2,
                             (cuuint64_t)HH * WW * C * 2,
                             (cuuint64_t)BATCH * HH * WW * C * 2};
    cuuint32_t box[5] = {64, WW, 8, 1, 1};
    cuuint32_t es[5]  = {1, 1, 1, 1, 1};
    get_enc()(tm, CU_TENSOR_MAP_DATA_TYPE_FLOAT16, 5, base, dims, strides, box, es,
              CU_TENSOR_MAP_INTERLEAVE_NONE, CU_TENSOR_MAP_SWIZZLE_NONE,
              CU_TENSOR_MAP_L2_PROMOTION_L2_128B, CU_TENSOR_MAP_FLOAT_OOB_FILL_NONE);
}
static void enc_w3(CUtensorMap* tm, void* base, int K) {
    cuuint64_t dims[3]    = {(cuuint64_t)K, GATES, 3};
    cuuint64_t strides[2] = {(cuuint64_t)K * 2, (cuuint64_t)GATES * K * 2};
    cuuint32_t box[3] = {64, 32, 1};
    cuuint32_t es[3]  = {1, 1, 1};
    get_enc()(tm, CU_TENSOR_MAP_DATA_TYPE_FLOAT16, 3, base, dims, strides, box, es,
              CU_TENSOR_MAP_INTERLEAVE_NONE, CU_TENSOR_MAP_SWIZZLE_NONE,
              CU_TENSOR_MAP_L2_PROMOTION_L2_128B, CU_TENSOR_MAP_FLOAT_OOB_FILL_NONE);
}

extern "C" void kernel_launch(void* const* d_in, const int* in_sizes, int n_in,
                              void* d_out, int out_size)
{
    const float* x  = (const float*)d_in[0];
    const float* hs = (const float*)d_in[1];
    const float* cs = (const float*)d_in[2];
    const float* Wx = (const float*)d_in[3];
    const float* Wh = (const float*)d_in[4];
    const float* bb = (const float*)d_in[5];

    float* out    = (float*)d_out;
    float* h_last = out;
    float* hs_out = out + PLANE;
    float* cs_out = out + 4 * PLANE;

    __half *WxT, *WhT, *xP, *hsP, *hbuf;
    float  *Gx, *cbuf;
    cudaGetSymbolAddress((void**)&WxT,  g_WxT);
    cudaGetSymbolAddress((void**)&WhT,  g_WhT);
    cudaGetSymbolAddress((void**)&xP,   g_xP);
    cudaGetSymbolAddress((void**)&hsP,  g_hsP);
    cudaGetSymbolAddress((void**)&Gx,   g_Gx);
    cudaGetSymbolAddress((void**)&hbuf, g_hbuf);
    cudaGetSymbolAddress((void**)&cbuf, g_cbuf);

    cudaFuncSetAttribute(conv_tc<1, 9, false, false>,
                         cudaFuncAttributeMaxDynamicSharedMemorySize, SMEM_TOTAL);
    cudaFuncSetAttribute(conv_tc<2, 18, true, true>,
                         cudaFuncAttributeMaxDynamicSharedMemorySize, SMEM_TOTAL);
    cudaFuncSetAttribute(conv_tc<2, 18, true, false>,
                         cudaFuncAttributeMaxDynamicSharedMemorySize, SMEM_TOTAL);

    CUtensorMap tm_x, tm_hs, tm_hb, tm_wx, tm_wh;
    enc_act5(&tm_x,  xP,   CIN_X, 1);
    enc_act5(&tm_hs, hsP,  HID,   3);
    enc_act5(&tm_hb, hbuf, HID,   6);   // [buf0 l0..l2 | buf1 l0..l2]
    enc_w3(&tm_wx, WxT, KX);
    enc_w3(&tm_wh, WhT, KH);

    // pre-passes
    {
        int tw = 3 * KX * GATES, th = 3 * KH * GATES;
        prep_w<<<(tw + 255) / 256, 256>>>(Wx, WxT, KX, tw);
        prep_w<<<(th + 255) / 256, 256>>>(Wh, WhT, KH, th);
        size_t px = (size_t)MPOS * (CIN_X / 2), ph = 3 * PLANE / 2;
        prep_a2<<<(unsigned)((px + 255) / 256), 256>>>(x,  xP,  CIN_X / 2, px);
        prep_a2<<<(unsigned)((ph + 255) / 256), 256>>>(hs, hsP, HID / 2,  ph);
    }

    const dim3 grid(MPOS / BM, 4, 3);        // all 3 layers per launch
    const size_t gxS = GXPLANE * 4;          // Gx per-layer bytes (fp32)
    const size_t pF  = PLANE * 4;            // fp32 plane bytes
    const size_t pH  = PLANE * 2;            // fp16 plane bytes

    // Gx[l] = conv(x, Wx[l]) + b[l]   (repeat-invariant)
    conv_tc<1, 9, false, false><<<grid, NTH, SMEM_TOTAL>>>(
        tm_x, tm_wx, 0, 0,
        (const char*)bb, GATES * 4,
        nullptr, 0,
        (char*)Gx, gxS,
        nullptr, 0, nullptr);

    // r0: hsP[l]/cs[l] -> hbuf[0][l] (fp16 perm) / cbuf[0][l]
    conv_tc<2, 18, true, true><<<grid, NTH, SMEM_TOTAL>>>(
        tm_hs, tm_wh, 0, 1,
        (const char*)Gx, gxS,
        (const char*)cs, pF,
        (char*)hbuf, pH,
        (char*)cbuf, pF, nullptr);

    // r1: hbuf[0][l]/cbuf[0][l] -> hbuf[1][l] / cbuf[1][l]
    conv_tc<2, 18, true, true><<<grid, NTH, SMEM_TOTAL>>>(
        tm_hb, tm_wh, 0, 1,
        (const char*)Gx, gxS,
        (const char*)cbuf, pF,
        (char*)(hbuf + 3 * PLANE), pH,
        (char*)(cbuf + 3 * PLANE), pF, nullptr);

    // r2: hbuf[1][l]/cbuf[1][l] -> output slices (fp32, natural order)
    conv_tc<2, 18, true, false><<<grid, NTH, SMEM_TOTAL>>>(
        tm_hb, tm_wh, 3, 1,
        (const char*)Gx, gxS,
        (const char*)(cbuf + 3 * PLANE), pF,
        (char*)hs_out, pF,
        (char*)cs_out, pF, h_last);
}

// round 15
// speedup vs baseline: 1.1126x; 1.0086x over previous
#include <cuda_runtime.h>
#include <cuda.h>
#include <cuda_fp16.h>
#include <cstdint>
#include <dlfcn.h>
#include <math.h>

// ---------------------------------------------------------------------------
// Problem: B=64, H=W=32, CIN=64, HID=128, K=3, L=3, repeats=3.
// Gates=512, M=65536. Out: [h_last | hs_out(3) | cs_out(3)].
// fp16 operands, fp32 accumulate/Gx. grid.z = layer (one launch per stage).
// 16 warps = 8(M) x 2(N), warp tile 32x64: 4 warps/SMSP for latency cover;
// smem bytes/chunk (1536 cyc) stay under the fp16 MMA floor (2048 cyc).
// ---------------------------------------------------------------------------
#define BATCH   64
#define HH      32
#define WW      32
#define CIN_X   64
#define HID     128
#define GATES   512
#define MPOS    (BATCH*HH*WW)
#define PLANE   ((size_t)MPOS*HID)
#define GXPLANE ((size_t)MPOS*GATES)
#define KX      (9*CIN_X)              // 576
#define KH      (9*HID)                // 1152

#define BM          256
#define NTH         512
#define NWARPS      16
#define STAGES      4
#define A_BYTES     32768
#define B_BYTES     16384
#define STAGE_BYTES (A_BYTES + B_BYTES)
#define SM_A(s)     ((s)*STAGE_BYTES)
#define SM_B(s)     (SM_A(s) + A_BYTES)
#define SM_BAR      (STAGES*STAGE_BYTES)
#define SMEM_TOTAL  (SM_BAR + 128)

// ---------------------------------------------------------------------------
// Device scratch
// ---------------------------------------------------------------------------
__device__ __align__(1024) __half g_WxT[3 * GATES * KX];
__device__ __align__(1024) __half g_WhT[3 * GATES * KH];
__device__ __align__(1024) __half g_xP [(size_t)MPOS * CIN_X];
__device__ __align__(1024) __half g_hsP[3 * PLANE];
__device__ __align__(1024) float  g_Gx [3 * GXPLANE];
__device__ __align__(1024) __half g_hbuf[2 * 3 * PLANE];   // [buf][layer]
__device__ __align__(1024) float  g_cbuf[2 * 3 * PLANE];

// ---------------------------------------------------------------------------
// PTX helpers
// ---------------------------------------------------------------------------
__device__ __forceinline__ uint32_t smem_u32(const void* p) {
    uint32_t a;
    asm("{ .reg .u64 t; cvta.to.shared.u64 t, %1; cvt.u32.u64 %0, t; }"
        : "=r"(a) : "l"(p));
    return a;
}
#define MBAR_INIT(addr, cnt) \
    asm volatile("mbarrier.init.shared.b64 [%0], %1;" :: "r"(addr), "r"(cnt) : "memory")
#define MBAR_ARRIVE(addr) \
    asm volatile("mbarrier.arrive.shared.b64 _, [%0];" :: "r"(addr) : "memory")
#define MBAR_EXPECT_TX(addr, bytes) \
    asm volatile("mbarrier.arrive.expect_tx.shared.b64 _, [%0], %1;" \
                 :: "r"(addr), "r"(bytes) : "memory")
#define MBAR_WAIT(addr, ph) do {                                              \
    uint32_t _m = (addr), _p = (ph), _d;                                      \
    asm volatile("{\n\t.reg .pred p;\n\t"                                     \
        "mbarrier.try_wait.parity.acquire.cta.shared::cta.b64 p, [%1], %2;\n\t" \
        "selp.b32 %0, 1, 0, p;\n\t}" : "=r"(_d) : "r"(_m), "r"(_p) : "memory");\
    if (!_d) {                                                                \
        asm volatile("{\n\t.reg .pred P1;\n\tWL_%=:\n\t"                      \
            "mbarrier.try_wait.parity.acquire.cta.shared::cta.b64 P1, [%0], %1, 0x989680;\n\t" \
            "@P1 bra.uni WD_%=;\n\tbra.uni WL_%=;\n\tWD_%=:\n\t}"             \
            :: "r"(_m), "r"(_p) : "memory");                                  \
    } } while (0)

#define TMA_LD_5D(dst, map, c0_, c1_, c2_, c3_, c4_, mbar) \
    asm volatile("cp.async.bulk.tensor.5d.shared::cta.global.tile.mbarrier::complete_tx::bytes " \
        "[%0], [%1, {%2, %3, %4, %5, %6}], [%7];" \
        :: "r"(dst), "l"(map), "r"(c0_), "r"(c1_), "r"(c2_), "r"(c3_), "r"(c4_), "r"(mbar) : "memory")
#define TMA_LD_3D(dst, map, c0_, c1_, c2_, mbar) \
    asm volatile("cp.async.bulk.tensor.3d.shared::cta.global.tile.mbarrier::complete_tx::bytes " \
        "[%0], [%1, {%2, %3, %4}], [%5];" \
        :: "r"(dst), "l"(map), "r"(c0_), "r"(c1_), "r"(c2_), "r"(mbar) : "memory")

__device__ __forceinline__ uint2 lds64(uint32_t addr) {
    uint2 r;
    asm("ld.shared.v2.b32 {%0,%1}, [%2];" : "=r"(r.x), "=r"(r.y) : "r"(addr));
    return r;
}

// m16n8k16 fp16 mma, fp32 accumulate
__device__ __forceinline__ void mma16(float* d, const uint32_t* a, const uint32_t* b) {
    asm volatile("mma.sync.aligned.m16n8k16.row.col.f32.f16.f16.f32 "
        "{%0,%1,%2,%3}, {%4,%5,%6,%7}, {%8,%9}, {%0,%1,%2,%3};"
        : "+f"(d[0]), "+f"(d[1]), "+f"(d[2]), "+f"(d[3])
        : "r"(a[0]), "r"(a[1]), "r"(a[2]), "r"(a[3]), "r"(b[0]), "r"(b[1]));
}

__device__ __forceinline__ int perm16(int k) {
    return 4 * ((k & 7) >> 1) + 2 * (k >> 3) + (k & 1);
}
__device__ __forceinline__ int bankperm64(int c, int row) {
    return ((((c >> 4) & 3) ^ (row & 3)) << 4) | perm16(c & 15);
}
__device__ __forceinline__ float sigm(float v) { return 1.f / (1.f + __expf(-v)); }

// ---------------------------------------------------------------------------
// Fused implicit-GEMM conv via fp16 mma.sync m16n8k16 (fp32 accum).
// grid = (M/BM, 4, 3): blockIdx.z = layer. 16 warps = 8(M) x 2(N), tile 32x64.
// Chunk = 64 fp16 channels. A swizzle key = global x&3 (dx-compensated).
// Each warp owns 2 sub-columns of EVERY gate -> fused epilogue thread-local.
// ---------------------------------------------------------------------------
template<int CPT, int NCHUNK, bool FUSED, bool PERM>
__global__ __launch_bounds__(NTH, 1)
void conv_tc(const __grid_constant__ CUtensorMap a_map,
             const __grid_constant__ CUtensorMap b_map,
             int a_z0, int a_zstep,
             const char* __restrict__ add_src, size_t add_stride,
             const char* __restrict__ c_in,    size_t cin_stride,
             char* __restrict__ out0,          size_t out0_stride,
             char* __restrict__ c_out,         size_t cout_stride,
             float* __restrict__ h_dup)        // only used when layer==2
{
    extern __shared__ __align__(1024) char smem[];
    const uint32_t sb = smem_u32(smem);
    const int tid  = threadIdx.x;
    const int lane = tid & 31;
    const int wid  = tid >> 5;
    const int wm   = wid & 7;            // M slice (32 rows)
    const int wn   = wid >> 3;           // N half (0/1)
    const int l    = blockIdx.z;
    const int a_z  = a_z0 + l * a_zstep;
    const int b_z  = l;

    const uint32_t FULL  = sb + SM_BAR;
    const uint32_t EMPTY = sb + SM_BAR + 32;

    if (tid == 0) {
#pragma unroll
        for (int s = 0; s < STAGES; s++) {
            MBAR_INIT(FULL + 8*s, 1);
            MBAR_INIT(EMPTY + 8*s, NWARPS);
        }
    }
    __syncthreads();

    const int c0   = blockIdx.y * 32;
    const int m0   = blockIdx.x * BM;
    const int bimg = m0 >> 10;
    const int y0   = (m0 >> 5) & 31;

    if (tid == 0) {
#pragma unroll
        for (int kc = 0; kc < STAGES; kc++) {
            const int s = kc;
            MBAR_EXPECT_TX(FULL + 8*s, (uint32_t)STAGE_BYTES);
            const int tap = kc / CPT, cc = (kc % CPT) * 64;
            const int dy = tap / 3 - 1, dx = tap % 3 - 1;
            TMA_LD_5D(sb + SM_A(s), &a_map, cc, dx, y0 + dy, bimg, a_z, FULL + 8*s);
            const int k0 = kc * 64;
#pragma unroll
            for (int g = 0; g < 4; g++)
                TMA_LD_3D(sb + SM_B(s) + g * 4096, &b_map, k0, g * 128 + c0, b_z,
                          FULL + 8*s);
        }
    }

    float acc[2][8][4];   // [mi][g*2+s2][frag]
#pragma unroll
    for (int mi = 0; mi < 2; mi++)
#pragma unroll
        for (int ni = 0; ni < 8; ni++)
#pragma unroll
            for (int j = 0; j < 4; j++) acc[mi][ni][j] = 0.f;

    const int q4 = lane >> 2;
    const int t4 = lane & 3;
    const uint32_t xorB = (uint32_t)(q4 & 3) << 5;

    for (int kc = 0; kc < NCHUNK; kc++) {
        const int s = kc & 3;
        const uint32_t u = (kc >> 2) & 1;
        MBAR_WAIT(FULL + 8*s, u);

        const int tap = kc / CPT;
        const int dxA = tap % 3 - 1;
        const uint32_t xorA = (uint32_t)((q4 + dxA) & 3) << 5;

        const uint32_t aW = sb + SM_A(s) + (uint32_t)wm * 4096 + ((uint32_t)q4 << 7);
        const uint32_t bW = sb + SM_B(s) + (uint32_t)wn * 2048 + ((uint32_t)q4 << 7);

#pragma unroll
        for (int ks = 0; ks < 4; ks++) {
            const uint32_t koffA = (((uint32_t)(ks * 32)) ^ xorA) + (uint32_t)(t4 * 8);
            const uint32_t koffB = (((uint32_t)(ks * 32)) ^ xorB) + (uint32_t)(t4 * 8);

            uint2 aLo[2], aHi[2];
#pragma unroll
            for (int mi = 0; mi < 2; mi++) {
                aLo[mi] = lds64(aW + (uint32_t)mi * 2048 + koffA);
                aHi[mi] = lds64(aW + (uint32_t)mi * 2048 + 1024 + koffA);
            }
            uint2 bfr[8];
#pragma unroll
            for (int g = 0; g < 4; g++)
#pragma unroll
                for (int s2 = 0; s2 < 2; s2++)
                    bfr[g*2+s2] = lds64(bW + (uint32_t)g * 4096
                                           + (uint32_t)s2 * 1024 + koffB);
#pragma unroll
            for (int mi = 0; mi < 2; mi++) {
                const uint32_t af[4] = {aLo[mi].x, aHi[mi].x, aLo[mi].y, aHi[mi].y};
#pragma unroll
                for (int ni = 0; ni < 8; ni++)
                    mma16(acc[mi][ni], af, &bfr[ni].x);
            }
        }

        if (lane == 0) MBAR_ARRIVE(EMPTY + 8*s);

        if (tid == 0 && kc + STAGES < NCHUNK) {
            MBAR_WAIT(EMPTY + 8*s, u);
            MBAR_EXPECT_TX(FULL + 8*s, (uint32_t)STAGE_BYTES);
            const int kn = kc + STAGES;
            const int tapn = kn / CPT, cc = (kn % CPT) * 64;
            const int dy = tapn / 3 - 1, dx = tapn % 3 - 1;
            TMA_LD_5D(sb + SM_A(s), &a_map, cc, dx, y0 + dy, bimg, a_z, FULL + 8*s);
            const int k0 = kn * 64;
#pragma unroll
            for (int g = 0; g < 4; g++)
                TMA_LD_3D(sb + SM_B(s) + g * 4096, &b_map, k0, g * 128 + c0, b_z,
                          FULL + 8*s);
        }
    }

    // ------------------------- epilogue -------------------------
    if (FUSED) {
        const float* gxl = (const float*)(add_src + (size_t)l * add_stride);
        const float* cil = (const float*)(c_in + (size_t)l * cin_stride);
        float*  coutl = (float*)(c_out + (size_t)l * cout_stride);
        __half* o16   = (__half*)(out0 + (size_t)l * out0_stride);
        float*  o32   = (float*)(out0 + (size_t)l * out0_stride);
        float*  hd    = (h_dup && l == 2) ? h_dup : nullptr;
#pragma unroll
        for (int mi = 0; mi < 2; mi++)
#pragma unroll
            for (int h = 0; h < 2; h++) {
                const int m = m0 + wm * 32 + mi * 16 + q4 + 8 * h;
                const int j = 2 * h;
#pragma unroll
                for (int s2 = 0; s2 < 2; s2++) {
                    const int nqe = wn * 2 + s2;
                    const int ch = c0 + nqe * 8 + t4 * 2;
                    const float* gxp = gxl + (size_t)m * GATES + ch;
                    const float2 gi = *(const float2*)(gxp);
                    const float2 gf = *(const float2*)(gxp + 128);
                    const float2 gg = *(const float2*)(gxp + 256);
                    const float2 go = *(const float2*)(gxp + 384);
                    const float2 cv = *(const float2*)(cil + (size_t)m * HID + ch);

                    const float i0 = acc[mi][s2][j]      + gi.x;
                    const float i1 = acc[mi][s2][j+1]    + gi.y;
                    const float f0 = acc[mi][2+s2][j]    + gf.x;
                    const float f1 = acc[mi][2+s2][j+1]  + gf.y;
                    const float g0 = acc[mi][4+s2][j]    + gg.x;
                    const float g1 = acc[mi][4+s2][j+1]  + gg.y;
                    const float o0 = acc[mi][6+s2][j]    + go.x;
                    const float o1 = acc[mi][6+s2][j+1]  + go.y;

                    float2 cn, hn;
                    cn.x = sigm(f0) * cv.x + sigm(i0) * tanhf(g0);
                    cn.y = sigm(f1) * cv.y + sigm(i1) * tanhf(g1);
                    hn.x = sigm(o0) * tanhf(cn.x);
                    hn.y = sigm(o1) * tanhf(cn.y);

                    const size_t ob = (size_t)m * HID + ch;
                    *(float2*)(coutl + ob) = cn;
                    if (PERM) {
                        const int c64 = ch & 63;
                        const int G   = (c64 >> 4) ^ (m & 3);
                        const int a2  = (c64 & 15) >> 1;
                        const int p   = 4 * (a2 & 3) + 2 * (a2 >> 2);
                        const int pos = (ch & ~63) + (G << 4) + p;
                        *(half2*)(o16 + (size_t)m * HID + pos) =
                            __floats2half2_rn(hn.x, hn.y);
                    } else {
                        *(float2*)(o32 + ob) = hn;
                        if (hd) *(float2*)(hd + ob) = hn;
                    }
                }
            }
    } else {
        const float* bl = (const float*)(add_src + (size_t)l * add_stride);
        float* gxo = (float*)(out0 + (size_t)l * out0_stride);
#pragma unroll
        for (int mi = 0; mi < 2; mi++)
#pragma unroll
            for (int h = 0; h < 2; h++) {
                const int m = m0 + wm * 32 + mi * 16 + q4 + 8 * h;
                const int j = 2 * h;
#pragma unroll
                for (int g = 0; g < 4; g++)
#pragma unroll
                    for (int s2 = 0; s2 < 2; s2++) {
                        const int gcol = g * 128 + c0 + (wn * 2 + s2) * 8 + t4 * 2;
                        const float2 bv = *(const float2*)(bl + gcol);
                        float2 v;
                        v.x = acc[mi][g*2+s2][j]   + bv.x;
                        v.y = acc[mi][g*2+s2][j+1] + bv.y;
                        *(float2*)(gxo + (size_t)m * GATES + gcol) = v;
                    }
            }
    }
}

// ---------------------------------------------------------------------------
// Pre-passes: fp32 -> fp16 with bank-swizzled 64-channel K layout.
// ---------------------------------------------------------------------------
__global__ void prep_w(const float* __restrict__ src, __half* __restrict__ dst,
                       int K, int total)
{
    int i = blockIdx.x * blockDim.x + threadIdx.x;
    if (i >= total) return;
    int n = i % GATES;
    int k = (i / GATES) % K;
    int l = i / (GATES * K);
    int kp = (k & ~63) | bankperm64(k & 63, n);
    dst[((size_t)l * GATES + n) * K + kp] = __float2half_rn(src[i]);
}

__global__ void prep_a2(const float* __restrict__ src, __half* __restrict__ dst,
                        int Cpairs, size_t totalPairs)
{
    size_t i = (size_t)blockIdx.x * blockDim.x + threadIdx.x;
    if (i >= totalPairs) return;
    const int cp2 = (int)(i % (size_t)Cpairs);
    const size_t row = i / (size_t)Cpairs;
    const int c = cp2 * 2;
    const int key = (int)(row & 3);
    const int pos = (c & ~63) | bankperm64(c & 63, key);
    const float2 v = *(const float2*)(src + row * (size_t)(Cpairs * 2) + c);
    *(half2*)(dst + row * (size_t)(Cpairs * 2) + pos) = __floats2half2_rn(v.x, v.y);
}

// ---------------------------------------------------------------------------
// Host: tensormap encoding via dlopen
// ---------------------------------------------------------------------------
typedef CUresult (*EncFn)(CUtensorMap*, CUtensorMapDataType, cuuint32_t, void*,
                          const cuuint64_t*, const cuuint64_t*, const cuuint32_t*,
                          const cuuint32_t*, CUtensorMapInterleave, CUtensorMapSwizzle,
                          CUtensorMapL2promotion, CUtensorMapFloatOOBfill);
static EncFn get_enc() {
    static EncFn f = nullptr;
    if (!f) {
        void* h = dlopen("libcuda.so.1", RTLD_NOW | RTLD_GLOBAL);
        if (!h) h = dlopen("libcuda.so", RTLD_NOW | RTLD_GLOBAL);
        if (h) f = (EncFn)dlsym(h, "cuTensorMapEncodeTiled");
    }
    return f;
}

static void enc_act5(CUtensorMap* tm, void* base, int C, int Z) {
    cuuint64_t dims[5]    = {(cuuint64_t)C, WW, HH, BATCH, (cuuint64_t)Z};
    cuuint64_t strides[4] = {(cuuint64_t)C * 2, (cuuint64_t)WW * C * 2,
                             (cuuint64_t)HH * WW * C * 2,
                             (cuuint64_t)BATCH * HH * WW * C * 2};
    cuuint32_t box[5] = {64, WW, 8, 1, 1};
    cuuint32_t es[5]  = {1, 1, 1, 1, 1};
    get_enc()(tm, CU_TENSOR_MAP_DATA_TYPE_FLOAT16, 5, base, dims, strides, box, es,
              CU_TENSOR_MAP_INTERLEAVE_NONE, CU_TENSOR_MAP_SWIZZLE_NONE,
              CU_TENSOR_MAP_L2_PROMOTION_L2_128B, CU_TENSOR_MAP_FLOAT_OOB_FILL_NONE);
}
static void enc_w3(CUtensorMap* tm, void* base, int K) {
    cuuint64_t dims[3]    = {(cuuint64_t)K, GATES, 3};
    cuuint64_t strides[2] = {(cuuint64_t)K * 2, (cuuint64_t)GATES * K * 2};
    cuuint32_t box[3] = {64, 32, 1};
    cuuint32_t es[3]  = {1, 1, 1};
    get_enc()(tm, CU_TENSOR_MAP_DATA_TYPE_FLOAT16, 3, base, dims, strides, box, es,
              CU_TENSOR_MAP_INTERLEAVE_NONE, CU_TENSOR_MAP_SWIZZLE_NONE,
              CU_TENSOR_MAP_L2_PROMOTION_L2_128B, CU_TENSOR_MAP_FLOAT_OOB_FILL_NONE);
}

extern "C" void kernel_launch(void* const* d_in, const int* in_sizes, int n_in,
                              void* d_out, int out_size)
{
    const float* x  = (const float*)d_in[0];
    const float* hs = (const float*)d_in[1];
    const float* cs = (const float*)d_in[2];
    const float* Wx = (const float*)d_in[3];
    const float* Wh = (const float*)d_in[4];
    const float* bb = (const float*)d_in[5];

    float* out    = (float*)d_out;
    float* h_last = out;
    float* hs_out = out + PLANE;
    float* cs_out = out + 4 * PLANE;

    __half *WxT, *WhT, *xP, *hsP, *hbuf;
    float  *Gx, *cbuf;
    cudaGetSymbolAddress((void**)&WxT,  g_WxT);
    cudaGetSymbolAddress((void**)&WhT,  g_WhT);
    cudaGetSymbolAddress((void**)&xP,   g_xP);
    cudaGetSymbolAddress((void**)&hsP,  g_hsP);
    cudaGetSymbolAddress((void**)&Gx,   g_Gx);
    cudaGetSymbolAddress((void**)&hbuf, g_hbuf);
    cudaGetSymbolAddress((void**)&cbuf, g_cbuf);

    cudaFuncSetAttribute(conv_tc<1, 9, false, false>,
                         cudaFuncAttributeMaxDynamicSharedMemorySize, SMEM_TOTAL);
    cudaFuncSetAttribute(conv_tc<2, 18, true, true>,
                         cudaFuncAttributeMaxDynamicSharedMemorySize, SMEM_TOTAL);
    cudaFuncSetAttribute(conv_tc<2, 18, true, false>,
                         cudaFuncAttributeMaxDynamicSharedMemorySize, SMEM_TOTAL);

    CUtensorMap tm_x, tm_hs, tm_hb, tm_wx, tm_wh;
    enc_act5(&tm_x,  xP,   CIN_X, 1);
    enc_act5(&tm_hs, hsP,  HID,   3);
    enc_act5(&tm_hb, hbuf, HID,   6);   // [buf0 l0..l2 | buf1 l0..l2]
    enc_w3(&tm_wx, WxT, KX);
    enc_w3(&tm_wh, WhT, KH);

    // pre-passes
    {
        int tw = 3 * KX * GATES, th = 3 * KH * GATES;
        prep_w<<<(tw + 255) / 256, 256>>>(Wx, WxT, KX, tw);
        prep_w<<<(th + 255) / 256, 256>>>(Wh, WhT, KH, th);
        size_t px = (size_t)MPOS * (CIN_X / 2), ph = 3 * PLANE / 2;
        prep_a2<<<(unsigned)((px + 255) / 256), 256>>>(x,  xP,  CIN_X / 2, px);
        prep_a2<<<(unsigned)((ph + 255) / 256), 256>>>(hs, hsP, HID / 2,  ph);
    }

    const dim3 grid(MPOS / BM, 4, 3);        // all 3 layers per launch
    const size_t gxS = GXPLANE * 4;          // Gx per-layer bytes (fp32)
    const size_t pF  = PLANE * 4;            // fp32 plane bytes
    const size_t pH  = PLANE * 2;            // fp16 plane bytes

    // Gx[l] = conv(x, Wx[l]) + b[l]   (repeat-invariant)
    conv_tc<1, 9, false, false><<<grid, NTH, SMEM_TOTAL>>>(
        tm_x, tm_wx, 0, 0,
        (const char*)bb, GATES * 4,
        nullptr, 0,
        (char*)Gx, gxS,
        nullptr, 0, nullptr);

    // r0: hsP[l]/cs[l] -> hbuf[0][l] (fp16 perm) / cbuf[0][l]
    conv_tc<2, 18, true, true><<<grid, NTH, SMEM_TOTAL>>>(
        tm_hs, tm_wh, 0, 1,
        (const char*)Gx, gxS,
        (const char*)cs, pF,
        (char*)hbuf, pH,
        (char*)cbuf, pF, nullptr);

    // r1: hbuf[0][l]/cbuf[0][l] -> hbuf[1][l] / cbuf[1][l]
    conv_tc<2, 18, true, true><<<grid, NTH, SMEM_TOTAL>>>(
        tm_hb, tm_wh, 0, 1,
        (const char*)Gx, gxS,
        (const char*)cbuf, pF,
        (char*)(hbuf + 3 * PLANE), pH,
        (char*)(cbuf + 3 * PLANE), pF, nullptr);

    // r2: hbuf[1][l]/cbuf[1][l] -> output slices (fp32, natural order)
    conv_tc<2, 18, true, false><<<grid, NTH, SMEM_TOTAL>>>(
        tm_hb, tm_wh, 3, 1,
        (const char*)Gx, gxS,
        (const char*)(cbuf + 3 * PLANE), pF,
        (char*)hs_out, pF,
        (char*)cs_out, pF, h_last);
}